// round 8
// baseline (speedup 1.0000x reference)
#include <cuda_runtime.h>
#include <cstdint>

#define NUM_EMBED 8192
#define ED 64
#define NTOK 32768
#define CH_STRIDE 4096
#define B_STRIDE 262144

#define OFF_LOSS 2097152
#define OFF_IDX  2097153
#define OFF_BIN  (2097153 + 32768)

#define MCTA 128                     /* tokens per CTA */
#define NCTA (NTOK / MCTA)           /* 256 */
#define NT 64                        /* codes per tile */
#define NTILES (NUM_EMBED / NT)      /* 128 */
#define CAP 64                       /* candidate slots per token */

#define ROWB 80                      /* padded smem row stride for int8 tiles */

__device__ float g_cnorm[NUM_EMBED * ED];              // [k][c] normalized codebook fp32
__device__ float g_zn[NTOK * ED];                      // [t][c] normalized z fp32
__device__ __align__(16) unsigned char g_Bq[(size_t)NUM_EMBED * 64]; // int8 codes
__device__ __align__(16) unsigned char g_Aq[(size_t)NTOK * 64];      // int8 z
__device__ int g_ea_i[NTOK];                           // per-token int error bound
__device__ int g_ebmax_i;                              // max per-code int error bound
__device__ float g_partial[NCTA];

// ===================== PTX helpers =====================
__device__ __forceinline__ uint32_t smem_u32(const void* p) {
    uint32_t a;
    asm("{ .reg .u64 t; cvta.to.shared.u64 t, %1; cvt.u32.u64 %0, t; }" : "=r"(a) : "l"(p));
    return a;
}
__device__ __forceinline__ void ldsm_x4(uint32_t* r, uint32_t addr) {
    asm volatile("ldmatrix.sync.aligned.m8n8.x4.shared.b16 {%0,%1,%2,%3}, [%4];"
        : "=r"(r[0]), "=r"(r[1]), "=r"(r[2]), "=r"(r[3]) : "r"(addr));
}
__device__ __forceinline__ void mma_s8(int* d, const uint32_t* a, uint32_t b0, uint32_t b1) {
    asm volatile("mma.sync.aligned.m16n8k32.row.col.s32.s8.s8.s32 "
        "{%0,%1,%2,%3}, {%4,%5,%6,%7}, {%8,%9}, {%0,%1,%2,%3};"
        : "+r"(d[0]), "+r"(d[1]), "+r"(d[2]), "+r"(d[3])
        : "r"(a[0]), "r"(a[1]), "r"(a[2]), "r"(a[3]), "r"(b0), "r"(b1));
}
#define CP_ASYNC16(dst, src) asm volatile("cp.async.cg.shared.global [%0], [%1], 16;" :: "r"(dst), "l"(src))
#define CP_COMMIT()          asm volatile("cp.async.commit_group;" ::: "memory")
#define CP_WAIT0()           asm volatile("cp.async.wait_group 0;" ::: "memory")
#define CP_WAIT1()           asm volatile("cp.async.wait_group 1;" ::: "memory")

// quantize + exact residual norm; returns int error bound (127^2 units)
__device__ __forceinline__ int pack_row_err(const float* x, uint32_t* w) {
    float es = 0.f;
#pragma unroll
    for (int j = 0; j < 16; ++j) {
        int q[4];
#pragma unroll
        for (int u = 0; u < 4; ++u) {
            float xv = x[4 * j + u];
            q[u] = __float2int_rn(127.f * xv);
            float e = xv - (float)q[u] * (1.f / 127.f);
            es = fmaf(e, e, es);
        }
        w[j] = (q[0] & 0xFF) | ((q[1] & 0xFF) << 8) | ((q[2] & 0xFF) << 16) | ((q[3] & 0xFF) << 24);
    }
    float en = __fsqrt_rn(es) * 1.02f + 1e-4f;
    return (int)(16129.f * en) + 16;
}

__global__ void k0_init() { g_ebmax_i = 0; }

// ===================== prep =====================
__global__ void k_prep_c(const float* __restrict__ ew) {
    int k = blockIdx.x * 128 + threadIdx.x;
    float v[64]; float ss = 0.f;
#pragma unroll
    for (int i = 0; i < 16; ++i) {
        float4 q = ((const float4*)(ew + (size_t)k * ED))[i];
        v[4*i+0] = q.x; v[4*i+1] = q.y; v[4*i+2] = q.z; v[4*i+3] = q.w;
        ss = fmaf(q.x, q.x, ss); ss = fmaf(q.y, q.y, ss);
        ss = fmaf(q.z, q.z, ss); ss = fmaf(q.w, q.w, ss);
    }
    float nm = fmaxf(__fsqrt_rn(ss), 1e-12f);
    float xn[64];
#pragma unroll
    for (int c = 0; c < 64; ++c) {
        xn[c] = __fdiv_rn(v[c], nm);
        g_cnorm[(size_t)k * ED + c] = xn[c];
    }
    uint32_t w[16];
    int eb = pack_row_err(xn, w);
    atomicMax(&g_ebmax_i, eb);
    uint4* dst = (uint4*)(g_Bq + (size_t)k * 64);
#pragma unroll
    for (int j = 0; j < 4; ++j) dst[j] = make_uint4(w[4*j], w[4*j+1], w[4*j+2], w[4*j+3]);
}

__global__ void k_prep_z(const float* __restrict__ z) {
    int t = blockIdx.x * 128 + threadIdx.x;
    int b = t >> 12, p = t & 4095;
    const float* zb = z + (size_t)b * B_STRIDE + p;
    float v[64]; float ss = 0.f;
#pragma unroll
    for (int c = 0; c < 64; ++c) { v[c] = zb[c * CH_STRIDE]; ss = fmaf(v[c], v[c], ss); }
    float nm = fmaxf(__fsqrt_rn(ss), 1e-12f);
    float xn[64];
#pragma unroll
    for (int c = 0; c < 64; ++c) xn[c] = __fdiv_rn(v[c], nm);
    float4* zd = (float4*)(g_zn + (size_t)t * 64);
#pragma unroll
    for (int j = 0; j < 16; ++j) zd[j] = make_float4(xn[4*j], xn[4*j+1], xn[4*j+2], xn[4*j+3]);
    uint32_t w[16];
    g_ea_i[t] = pack_row_err(xn, w);
    uint4* dst = (uint4*)(g_Aq + (size_t)t * 64);
#pragma unroll
    for (int j = 0; j < 4; ++j) dst[j] = make_uint4(w[4*j], w[4*j+1], w[4*j+2], w[4*j+3]);
}

// ===================== megakernel: filter + resolve + epilogue =====================
#define SMA 0
#define SMB0 10240
#define SMB1 15360
#define SMZN 20480                    /* 128 * 68 * 4 = 34816 ; reused as zraw [c][t] 64*128*4 */
#define SMCNT 55296                   /* 128*4 */
#define SMCAND 55808                  /* 128*64*2 = 16384 */
#define SMIDX 72192                   /* 128*4 */
#define SMRED 72704                   /* 256*4 */
#define SMBVR 73728                   /* 256*4 */
#define SMBIR 74752                   /* 256*4 */
#define SMTOT 75776

__global__ __launch_bounds__(256, 2) void k_main(const float* __restrict__ z,
                                                 const float* __restrict__ ew,
                                                 float* __restrict__ out_zq,
                                                 float* __restrict__ out_idx,
                                                 float* __restrict__ out_bin) {
    extern __shared__ char smem[];
    uint32_t sbase = smem_u32(smem);
    float* zs = (float*)(smem + SMZN);            // [tok][68]
    int* cnt = (int*)(smem + SMCNT);
    unsigned short* cand = (unsigned short*)(smem + SMCAND);
    int* idxs = (int*)(smem + SMIDX);
    float* red = (float*)(smem + SMRED);
    float* bvr = (float*)(smem + SMBVR);
    int* bir = (int*)(smem + SMBIR);

    const int tid = threadIdx.x, wid = tid >> 5, lane = tid & 31;
    const int tok0 = blockIdx.x * MCTA;
    const int b = tok0 >> 12, p0 = tok0 & 4095;

    for (int i = tid; i < MCTA; i += 256) cnt[i] = 0;

    // A prologue + B tile 0 via cp.async
    const unsigned char* Ag = g_Aq + (size_t)tok0 * 64;
    for (int i = tid; i < MCTA * 4; i += 256) {
        int row = i >> 2, c = i & 3;
        CP_ASYNC16(sbase + SMA + row * ROWB + c * 16, Ag + (size_t)row * 64 + c * 16);
    }
    for (int i = tid; i < NT * 4; i += 256) {
        int row = i >> 2, c = i & 3;
        CP_ASYNC16(sbase + SMB0 + row * ROWB + c * 16, g_Bq + (size_t)row * 64 + c * 16);
    }
    CP_COMMIT();

    // normalized z rows into smem (padded stride 68)
    for (int i = tid; i < MCTA * 64; i += 256) {
        int tk = i >> 6, c = i & 63;
        zs[tk * 68 + c] = g_zn[(size_t)(tok0 + tk) * 64 + c];
    }

    // ldmatrix lane mapping (proven R6/R7)
    const int lg = lane >> 3;
    const int lrow = ((lg & 1) << 3) + (lane & 7);
    const int lkc  = (lg >> 1) << 3;
    const int mrow0 = wid * 16;
    const uint32_t aaddr = sbase + SMA + (uint32_t)(mrow0 + lrow) * ROWB + lkc * 2;
    const uint32_t brel0 = (uint32_t)(0  + lrow) * ROWB + lkc * 2;
    const uint32_t brel1 = (uint32_t)(16 + lrow) * ROWB + lkc * 2;
    const uint32_t brel2 = (uint32_t)(32 + lrow) * ROWB + lkc * 2;
    const uint32_t brel3 = (uint32_t)(48 + lrow) * ROWB + lkc * 2;
    const int kcol0 = (lane & 3) << 1;
    const int row0 = mrow0 + (lane >> 2);

    const int ebm = g_ebmax_i;
    const int win0 = 2 * (g_ea_i[tok0 + row0] + ebm) + 64;
    const int win1 = 2 * (g_ea_i[tok0 + row0 + 8] + ebm) + 64;

    int rmax0 = -1073741824, rmax1 = -1073741824;
    __syncthreads();   // zs + cnt ready (A/B still in flight under cp.async group)

    // ---------------- single-phase IMMA sweep with running-max push ----------------
    for (int nt = 0; nt < NTILES; ++nt) {
        if (nt + 1 < NTILES) {
            uint32_t dstb = sbase + (((nt + 1) & 1) ? SMB1 : SMB0);
            const unsigned char* src = g_Bq + (size_t)(nt + 1) * NT * 64;
            for (int i = tid; i < NT * 4; i += 256) {
                int row = i >> 2, c = i & 3;
                CP_ASYNC16(dstb + row * ROWB + c * 16, src + (size_t)row * 64 + c * 16);
            }
            CP_COMMIT();
            CP_WAIT1();
        } else {
            CP_WAIT0();
        }
        __syncthreads();

        uint32_t bbuf = sbase + ((nt & 1) ? SMB1 : SMB0);
        int acc[8][4];
#pragma unroll
        for (int nf = 0; nf < 8; ++nf)
#pragma unroll
            for (int r = 0; r < 4; ++r) acc[nf][r] = 0;

#pragma unroll
        for (int ks = 0; ks < 2; ++ks) {
            uint32_t a0[4], bf0[4], bf1[4], bf2[4], bf3[4];
            ldsm_x4(a0, aaddr + ks * 32);
            ldsm_x4(bf0, bbuf + brel0 + ks * 32);
            ldsm_x4(bf1, bbuf + brel1 + ks * 32);
            ldsm_x4(bf2, bbuf + brel2 + ks * 32);
            ldsm_x4(bf3, bbuf + brel3 + ks * 32);
            mma_s8(acc[0], a0, bf0[0], bf0[2]);
            mma_s8(acc[1], a0, bf0[1], bf0[3]);
            mma_s8(acc[2], a0, bf1[0], bf1[2]);
            mma_s8(acc[3], a0, bf1[1], bf1[3]);
            mma_s8(acc[4], a0, bf2[0], bf2[2]);
            mma_s8(acc[5], a0, bf2[1], bf2[3]);
            mma_s8(acc[6], a0, bf3[0], bf3[2]);
            mma_s8(acc[7], a0, bf3[1], bf3[3]);
        }

        // merge tile max into running max (quad shares token rows)
        int tmax0 = -1073741824, tmax1 = -1073741824;
#pragma unroll
        for (int nf = 0; nf < 8; ++nf) {
            tmax0 = max(tmax0, max(acc[nf][0], acc[nf][1]));
            tmax1 = max(tmax1, max(acc[nf][2], acc[nf][3]));
        }
        tmax0 = max(tmax0, __shfl_xor_sync(0xffffffffu, tmax0, 1));
        tmax0 = max(tmax0, __shfl_xor_sync(0xffffffffu, tmax0, 2));
        tmax1 = max(tmax1, __shfl_xor_sync(0xffffffffu, tmax1, 1));
        tmax1 = max(tmax1, __shfl_xor_sync(0xffffffffu, tmax1, 2));
        rmax0 = max(rmax0, tmax0);
        rmax1 = max(rmax1, tmax1);
        const int thr0 = rmax0 - win0;
        const int thr1 = rmax1 - win1;

        int kbase = nt * NT + kcol0;
#pragma unroll
        for (int nf = 0; nf < 8; ++nf) {
            int kk = kbase + nf * 8;
            if (acc[nf][0] >= thr0) {
                int pos = atomicAdd(&cnt[row0], 1);
                if (pos < CAP) cand[row0 * CAP + pos] = (unsigned short)kk;
            }
            if (acc[nf][1] >= thr0) {
                int pos = atomicAdd(&cnt[row0], 1);
                if (pos < CAP) cand[row0 * CAP + pos] = (unsigned short)(kk + 1);
            }
            if (acc[nf][2] >= thr1) {
                int pos = atomicAdd(&cnt[row0 + 8], 1);
                if (pos < CAP) cand[(row0 + 8) * CAP + pos] = (unsigned short)kk;
            }
            if (acc[nf][3] >= thr1) {
                int pos = atomicAdd(&cnt[row0 + 8], 1);
                if (pos < CAP) cand[(row0 + 8) * CAP + pos] = (unsigned short)(kk + 1);
            }
        }
        __syncthreads();
    }

    // ---------------- in-kernel exact resolve (2 threads per token) ----------------
    {
        int tk = tid >> 1, par = tid & 1;
        int n = cnt[tk];
        float bv = -1e30f; int bi = 0x7FFFFFFF;
        if (n <= CAP) {
            const float* za = zs + tk * 68;
            for (int j = par; j < n; j += 2) {
                int k = cand[tk * CAP + j];
                const float4* cr4 = (const float4*)(g_cnorm + (size_t)k * ED);
                float d = 0.f;
#pragma unroll
                for (int m = 0; m < 16; ++m) {
                    float4 u = cr4[m];
                    d = fmaf(za[4*m+0], u.x, d);
                    d = fmaf(za[4*m+1], u.y, d);
                    d = fmaf(za[4*m+2], u.z, d);
                    d = fmaf(za[4*m+3], u.w, d);
                }
                if (d > bv || (d == bv && k < bi)) { bv = d; bi = k; }
            }
        }
        float ov = __shfl_xor_sync(0xffffffffu, bv, 1);
        int   oi = __shfl_xor_sync(0xffffffffu, bi, 1);
        if (ov > bv || (ov == bv && oi < bi)) { bv = ov; bi = oi; }
        if (par == 0) idxs[tk] = bi;
    }
    __syncthreads();

    // overflow tokens: full exact scan (vanishingly rare; rigor backstop)
    for (int tk = 0; tk < MCTA; ++tk) {
        if (cnt[tk] > CAP) {
            const float* za = zs + tk * 68;
            float bv = -1e30f; int bi = 0x7FFFFFFF;
            for (int k = tid; k < NUM_EMBED; k += 256) {
                const float4* cr4 = (const float4*)(g_cnorm + (size_t)k * ED);
                float d = 0.f;
#pragma unroll
                for (int m = 0; m < 16; ++m) {
                    float4 u = cr4[m];
                    d = fmaf(za[4*m+0], u.x, d);
                    d = fmaf(za[4*m+1], u.y, d);
                    d = fmaf(za[4*m+2], u.z, d);
                    d = fmaf(za[4*m+3], u.w, d);
                }
                if (d > bv || (d == bv && k < bi)) { bv = d; bi = k; }
            }
            bvr[tid] = bv; bir[tid] = bi;
            __syncthreads();
            for (int s = 128; s > 0; s >>= 1) {
                if (tid < s) {
                    float v2 = bvr[tid + s]; int i2 = bir[tid + s];
                    if (v2 > bvr[tid] || (v2 == bvr[tid] && i2 < bir[tid])) {
                        bvr[tid] = v2; bir[tid] = i2;
                    }
                }
                __syncthreads();
            }
            if (tid == 0) idxs[tk] = bir[0];
            __syncthreads();
        }
    }
    __syncthreads();

    // ---------------- epilogue: reload raw z [c][t], gather/STE/loss/idx/bin ----------------
    float* zr = (float*)(smem + SMZN);   // reuse: [c][128]
    const float* zb = z + (size_t)b * B_STRIDE + p0;
    for (int i = tid; i < 64 * 32; i += 256) {
        int c = i >> 5, q4 = i & 31;
        float4 v = ((const float4*)(zb + c * CH_STRIDE))[q4];
        ((float4*)(zr + c * 128))[q4] = v;
    }
    __syncthreads();

    {
        int half = tid >> 7;              // 0: ch 0..31, 1: ch 32..63
        int tk = tid & 127;
        int myidx = idxs[tk];
        const float4* er = (const float4*)(ew + (size_t)myidx * ED + half * 32);
        float ssq = 0.f;
#pragma unroll
        for (int m = 0; m < 8; ++m) {
            float4 e = er[m];
            float ev[4] = {e.x, e.y, e.z, e.w};
#pragma unroll
            for (int u = 0; u < 4; ++u) {
                int ch = half * 32 + m * 4 + u;
                float zc = zr[ch * 128 + tk];
                float d  = ev[u] - zc;
                out_zq[(size_t)(b * 64 + ch) * 4096 + p0 + tk] = zc + d;
                ssq = fmaf(d, d, ssq);
            }
        }
        red[tid] = ssq;
    }
    __syncthreads();
    for (int s = 128; s > 0; s >>= 1) {
        if (tid < s) red[tid] += red[tid + s];
        __syncthreads();
    }
    if (tid == 0) g_partial[blockIdx.x] = red[0];

    if (tid < MCTA) {
        out_idx[tok0 + tid] = (float)idxs[tid];
        atomicAdd(&out_bin[idxs[tid]], 1.0f);
    }
}

// ---------------- loss finalize ----------------
__global__ void k4_loss(float* __restrict__ out_loss) {
    int lane = threadIdx.x;
    float s = 0.f;
    for (int i = lane * 8; i < lane * 8 + 8; ++i) s += g_partial[i];
#pragma unroll
    for (int off = 16; off > 0; off >>= 1)
        s += __shfl_xor_sync(0xffffffffu, s, off);
    if (lane == 0) {
        float m = s / 2097152.0f;
        out_loss[0] = 0.25f * m + m;
    }
}

extern "C" void kernel_launch(void* const* d_in, const int* in_sizes, int n_in,
                              void* d_out, int out_size) {
    const float* z  = (const float*)d_in[0];
    const float* ew = (const float*)d_in[1];
    float* out      = (float*)d_out;

    float* out_zq   = out;
    float* out_loss = out + OFF_LOSS;
    float* out_idx  = out + OFF_IDX;
    float* out_bin  = out + OFF_BIN;

    cudaMemsetAsync(out_bin, 0, NUM_EMBED * sizeof(float));

    k0_init<<<1, 1>>>();
    k_prep_c<<<NUM_EMBED / 128, 128>>>(ew);
    k_prep_z<<<NTOK / 128, 128>>>(z);

    cudaFuncSetAttribute(k_main, cudaFuncAttributeMaxDynamicSharedMemorySize, SMTOT);
    k_main<<<NCTA, 256, SMTOT>>>(z, ew, out_zq, out_idx, out_bin);

    k4_loss<<<1, 32>>>(out_loss);
}

// round 9
// speedup vs baseline: 5.6271x; 5.6271x over previous
#include <cuda_runtime.h>
#include <cstdint>

#define NUM_EMBED 8192
#define ED 64
#define NTOK 32768
#define CH_STRIDE 4096
#define B_STRIDE 262144

#define OFF_LOSS 2097152
#define OFF_IDX  2097153
#define OFF_BIN  (2097153 + 32768)

#define MCTA 32                      /* tokens per CTA */
#define NBLK (NTOK / MCTA)           /* 1024 */
#define KB 128                       /* codes per tile */
#define NTILES (NUM_EMBED / KB)      /* 64 */
#define CAP 96                       /* candidate slots per token */

__device__ float g_cnorm[NUM_EMBED * ED];                 // [k][c] normalized codebook fp32
__device__ __align__(16) uint32_t g_Wq8[16 * NUM_EMBED];  // [cg][k] packed int8 codes
__device__ int g_ebmax_i;                                 // max per-code int error bound
__device__ float g_partial[NBLK];

// ===================== PTX helpers =====================
__device__ __forceinline__ uint32_t smem_u32(const void* p) {
    uint32_t a;
    asm("{ .reg .u64 t; cvta.to.shared.u64 t, %1; cvt.u32.u64 %0, t; }" : "=r"(a) : "l"(p));
    return a;
}
__device__ __forceinline__ int dp4a_(int a, int b, int c) {
    int d;
    asm("dp4a.s32.s32 %0, %1, %2, %3;" : "=r"(d) : "r"(a), "r"(b), "r"(c));
    return d;
}
#define CP_ASYNC16(dst, src) asm volatile("cp.async.cg.shared.global [%0], [%1], 16;" :: "r"(dst), "l"(src))
#define CP_COMMIT()          asm volatile("cp.async.commit_group;" ::: "memory")
#define CP_WAIT0()           asm volatile("cp.async.wait_group 0;" ::: "memory")

// quantize one normalized 64-vector; returns int error bound (127^2 units)
__device__ __forceinline__ int pack_row_err(const float* x, int xstride, uint32_t* w) {
    float es = 0.f;
#pragma unroll
    for (int j = 0; j < 16; ++j) {
        int q[4];
#pragma unroll
        for (int u = 0; u < 4; ++u) {
            float xv = x[(4 * j + u) * xstride];
            q[u] = __float2int_rn(127.f * xv);
            float e = xv - (float)q[u] * (1.f / 127.f);
            es = fmaf(e, e, es);
        }
        w[j] = (q[0] & 0xFF) | ((q[1] & 0xFF) << 8) | ((q[2] & 0xFF) << 16) | ((q[3] & 0xFF) << 24);
    }
    float en = __fsqrt_rn(es) * 1.02f + 1e-4f;
    return (int)(16129.f * en) + 16;
}

__global__ void k0_init() { g_ebmax_i = 0; }

// ===================== prep: normalize + quantize codebook =====================
__global__ void k_prep_c(const float* __restrict__ ew) {
    int k = blockIdx.x * 128 + threadIdx.x;
    float v[64]; float ss = 0.f;
#pragma unroll
    for (int i = 0; i < 16; ++i) {
        float4 q = ((const float4*)(ew + (size_t)k * ED))[i];
        v[4*i+0] = q.x; v[4*i+1] = q.y; v[4*i+2] = q.z; v[4*i+3] = q.w;
        ss = fmaf(q.x, q.x, ss); ss = fmaf(q.y, q.y, ss);
        ss = fmaf(q.z, q.z, ss); ss = fmaf(q.w, q.w, ss);
    }
    float nm = fmaxf(__fsqrt_rn(ss), 1e-12f);
    float xn[64];
#pragma unroll
    for (int c = 0; c < 64; ++c) {
        xn[c] = __fdiv_rn(v[c], nm);
        g_cnorm[(size_t)k * ED + c] = xn[c];
    }
    uint32_t w[16];
    int eb = pack_row_err(xn, 1, w);
    atomicMax(&g_ebmax_i, eb);
#pragma unroll
    for (int cg = 0; cg < 16; ++cg) g_Wq8[cg * NUM_EMBED + k] = w[cg];
}

// ===================== megakernel =====================
// CTA: 32 tokens, 128 threads; warp owns 8 tokens, lane owns 4 codes per KB=128 tile.
#define SM_WQ0  0                     /* 16*128*4 = 8192 */
#define SM_WQ1  8192                  /* 8192 */
#define SM_ZQ   16384                 /* 16*32*4 = 2048 packed z int8 [cg][t] */
#define SM_ZRAW 18432                 /* 64*32*4 = 8192 raw z [c][t] */
#define SM_ZS   26624                 /* 32*68*4 = 8704 normalized z [t][68] */
#define SM_NM   35328                 /* 32*4 */
#define SM_WT   35456                 /* 32*4 window per token */
#define SM_CNT  35584                 /* 32*4 */
#define SM_IDX  35712                 /* 32*4 */
#define SM_CAND 35840                 /* 32*96*2 = 6144 */
#define SM_RED  41984                 /* 128*4 */
#define SM_BV   42496                 /* 128*4 */
#define SM_BI   43008                 /* 128*4 */
#define SM_TOT  43520

__global__ __launch_bounds__(128, 2) void k_main(const float* __restrict__ z,
                                                 const float* __restrict__ ew,
                                                 float* __restrict__ out_zq,
                                                 float* __restrict__ out_idx,
                                                 float* __restrict__ out_bin) {
    extern __shared__ char sm_[];
    uint32_t sbase = smem_u32(sm_);
    uint32_t* zq8  = (uint32_t*)(sm_ + SM_ZQ);
    float*    zraw = (float*)(sm_ + SM_ZRAW);
    float*    zs   = (float*)(sm_ + SM_ZS);
    float*    nm   = (float*)(sm_ + SM_NM);
    int*      Wt   = (int*)(sm_ + SM_WT);
    int*      cnt  = (int*)(sm_ + SM_CNT);
    int*      idxs = (int*)(sm_ + SM_IDX);
    unsigned short* cand = (unsigned short*)(sm_ + SM_CAND);
    float*    red  = (float*)(sm_ + SM_RED);
    float*    bvr  = (float*)(sm_ + SM_BV);
    int*      bir  = (int*)(sm_ + SM_BI);

    const int tid  = threadIdx.x;
    const int warp = tid >> 5;
    const int lane = tid & 31;

    const int tok0 = blockIdx.x * MCTA;
    const int b    = tok0 >> 12;
    const int p0   = tok0 & 4095;
    const float* zb = z + (size_t)b * B_STRIDE + p0;

    // prefetch codebook tile 0 (16 cg rows x 512B)
    for (int i = tid; i < 16 * 32; i += 128) {
        int cg = i >> 5, q = i & 31;
        CP_ASYNC16(sbase + SM_WQ0 + (cg * KB + q * 4) * 4,
                   (const char*)(g_Wq8 + (size_t)cg * NUM_EMBED) + q * 16);
    }
    CP_COMMIT();

    if (tid < 32) cnt[tid] = 0;

    // load raw z tile [c][32]  (identical to proven R4 code)
    for (int i = tid; i < 512; i += 128) {
        int c = i >> 3, q = i & 7;
        float4 v = ((const float4*)(zb + c * CH_STRIDE))[q];
        ((float4*)(zraw + c * 32))[q] = v;
    }
    __syncthreads();

    // per-token norms (identical op order to R1/R4)
    if (tid < 32) {
        float ss = 0.f;
        for (int c = 0; c < 64; ++c) {
            float x = zraw[c * 32 + tid];
            ss = fmaf(x, x, ss);
        }
        nm[tid] = fmaxf(__fsqrt_rn(ss), 1e-12f);
    }
    __syncthreads();

    // normalized z [t][68] (same per-element division as R4)
    for (int i = tid; i < 64 * 32; i += 128) {
        int t = i & 31, c = i >> 5;
        zs[t * 68 + c] = __fdiv_rn(zraw[i], nm[t]);
    }
    __syncthreads();

    // per-token int8 pack + window
    if (tid < 32) {
        uint32_t w[16];
        int ea = pack_row_err(zs + tid * 68, 1, w);
#pragma unroll
        for (int cg = 0; cg < 16; ++cg) zq8[cg * 32 + tid] = w[cg];
        Wt[tid] = 2 * (ea + g_ebmax_i) + 64;
    }
    __syncthreads();

    const int t0 = warp * 8;
    int wtr[8];
#pragma unroll
    for (int t = 0; t < 8; ++t) wtr[t] = Wt[t0 + t];

    int rm[8];
#pragma unroll
    for (int t = 0; t < 8; ++t) rm[t] = -1073741824;

    const int kc0 = lane * 4;

    // ---------------- dp4a sweep with rigorous candidate push ----------------
    for (int nt = 0; nt < NTILES; ++nt) {
        CP_WAIT0();
        __syncthreads();

        const uint32_t* wq = (nt & 1) ? (uint32_t*)(sm_ + SM_WQ1) : (uint32_t*)(sm_ + SM_WQ0);

        if (nt + 1 < NTILES) {
            uint32_t wsN = (nt & 1) ? (sbase + SM_WQ0) : (sbase + SM_WQ1);
            const char* src0 = (const char*)(g_Wq8 + (size_t)(nt + 1) * KB);
            for (int i = tid; i < 16 * 32; i += 128) {
                int cg = i >> 5, q = i & 31;
                CP_ASYNC16(wsN + (cg * KB + q * 4) * 4,
                           src0 + (size_t)cg * NUM_EMBED * 4 + q * 16);
            }
            CP_COMMIT();
        }

        int acc[8][4];
#pragma unroll
        for (int t = 0; t < 8; ++t)
#pragma unroll
            for (int c = 0; c < 4; ++c) acc[t][c] = 0;

#pragma unroll
        for (int cg = 0; cg < 16; ++cg) {
            const uint32_t* zp = zq8 + cg * 32 + t0;
            uint4 a0 = *(const uint4*)(zp + 0);
            uint4 a1 = *(const uint4*)(zp + 4);
            uint4 wb = *(const uint4*)(wq + cg * KB + kc0);
            uint32_t aa[8] = {a0.x, a0.y, a0.z, a0.w, a1.x, a1.y, a1.z, a1.w};
            uint32_t bb[4] = {wb.x, wb.y, wb.z, wb.w};
#pragma unroll
            for (int t = 0; t < 8; ++t)
#pragma unroll
                for (int c = 0; c < 4; ++c)
                    acc[t][c] = dp4a_((int)aa[t], (int)bb[c], acc[t][c]);
        }

        // per-token tile max, merged across all 32 lanes, into running max
#pragma unroll
        for (int t = 0; t < 8; ++t) {
            int m = max(max(acc[t][0], acc[t][1]), max(acc[t][2], acc[t][3]));
#pragma unroll
            for (int off = 16; off > 0; off >>= 1)
                m = max(m, __shfl_xor_sync(0xffffffffu, m, off));
            rm[t] = max(rm[t], m);
        }

        // push candidates within window of running max (superset of final set)
        int kbase = nt * KB + kc0;
#pragma unroll
        for (int t = 0; t < 8; ++t) {
            int thr = rm[t] - wtr[t];
#pragma unroll
            for (int c = 0; c < 4; ++c) {
                if (acc[t][c] >= thr) {
                    int pos = atomicAdd(&cnt[t0 + t], 1);
                    if (pos < CAP) cand[(t0 + t) * CAP + pos] = (unsigned short)(kbase + c);
                }
            }
        }
    }
    __syncthreads();

    // ---------------- exact fp32 resolve (4 threads per token) ----------------
    {
        int tk = tid >> 2, q = tid & 3;
        int n = cnt[tk];
        float bv = -1e30f; int bi = 0x7FFFFFFF;
        if (n <= CAP) {
            const float* za = zs + tk * 68;
            for (int j = q; j < n; j += 4) {
                int k = cand[tk * CAP + j];
                const float4* cr4 = (const float4*)(g_cnorm + (size_t)k * ED);
                float d = 0.f;
#pragma unroll
                for (int m = 0; m < 16; ++m) {
                    float4 u = cr4[m];
                    d = fmaf(za[4*m+0], u.x, d);
                    d = fmaf(za[4*m+1], u.y, d);
                    d = fmaf(za[4*m+2], u.z, d);
                    d = fmaf(za[4*m+3], u.w, d);
                }
                if (d > bv || (d == bv && k < bi)) { bv = d; bi = k; }
            }
        }
#pragma unroll
        for (int off = 1; off <= 2; off <<= 1) {
            float ov = __shfl_xor_sync(0xffffffffu, bv, off);
            int   oi = __shfl_xor_sync(0xffffffffu, bi, off);
            if (ov > bv || (ov == bv && oi < bi)) { bv = ov; bi = oi; }
        }
        if (q == 0) idxs[tk] = bi;
    }
    __syncthreads();

    // overflow backstop: full exact scan (rigor guarantee; ~never triggers)
    for (int tk = 0; tk < MCTA; ++tk) {
        if (cnt[tk] > CAP) {
            const float* za = zs + tk * 68;
            float bv = -1e30f; int bi = 0x7FFFFFFF;
            for (int k = tid; k < NUM_EMBED; k += 128) {
                const float4* cr4 = (const float4*)(g_cnorm + (size_t)k * ED);
                float d = 0.f;
#pragma unroll
                for (int m = 0; m < 16; ++m) {
                    float4 u = cr4[m];
                    d = fmaf(za[4*m+0], u.x, d);
                    d = fmaf(za[4*m+1], u.y, d);
                    d = fmaf(za[4*m+2], u.z, d);
                    d = fmaf(za[4*m+3], u.w, d);
                }
                if (d > bv || (d == bv && k < bi)) { bv = d; bi = k; }
            }
            bvr[tid] = bv; bir[tid] = bi;
            __syncthreads();
            for (int s = 64; s > 0; s >>= 1) {
                if (tid < s) {
                    float v2 = bvr[tid + s]; int i2 = bir[tid + s];
                    if (v2 > bvr[tid] || (v2 == bvr[tid] && i2 < bir[tid])) {
                        bvr[tid] = v2; bir[tid] = i2;
                    }
                }
                __syncthreads();
            }
            if (tid == 0) idxs[tk] = bir[0];
            __syncthreads();
        }
    }
    __syncthreads();

    // ---------------- fused epilogue (proven R4): gather/STE/loss/idx/bin ----------------
    int myidx = idxs[lane];
    const float4* er = (const float4*)(ew + (size_t)myidx * ED + warp * 16);
    float4 e0 = er[0], e1 = er[1], e2 = er[2], e3 = er[3];
    float vals[16] = {e0.x, e0.y, e0.z, e0.w, e1.x, e1.y, e1.z, e1.w,
                      e2.x, e2.y, e2.z, e2.w, e3.x, e3.y, e3.z, e3.w};
    float ssq = 0.f;
#pragma unroll
    for (int j = 0; j < 16; ++j) {
        int ch = warp * 16 + j;
        float zc = zraw[ch * 32 + lane];
        float d  = vals[j] - zc;
        out_zq[(size_t)(b * 64 + ch) * 4096 + p0 + lane] = zc + d;
        ssq = fmaf(d, d, ssq);
    }
    red[tid] = ssq;
    __syncthreads();
    for (int s = 64; s > 0; s >>= 1) {
        if (tid < s) red[tid] += red[tid + s];
        __syncthreads();
    }
    if (tid == 0) g_partial[blockIdx.x] = red[0];

    if (tid < 32) {
        out_idx[tok0 + tid] = (float)idxs[tid];
        atomicAdd(&out_bin[idxs[tid]], 1.0f);
    }
}

// ---------------- loss finalize (proven R4) ----------------
__global__ void k4_loss(float* __restrict__ out_loss) {
    int lane = threadIdx.x;
    float s = 0.f;
    for (int i = lane * 32; i < lane * 32 + 32; ++i) s += g_partial[i];
#pragma unroll
    for (int off = 16; off > 0; off >>= 1)
        s += __shfl_xor_sync(0xffffffffu, s, off);
    if (lane == 0) {
        float m = s / 2097152.0f;
        out_loss[0] = 0.25f * m + m;
    }
}

extern "C" void kernel_launch(void* const* d_in, const int* in_sizes, int n_in,
                              void* d_out, int out_size) {
    const float* z  = (const float*)d_in[0];
    const float* ew = (const float*)d_in[1];
    float* out      = (float*)d_out;

    float* out_zq   = out;
    float* out_loss = out + OFF_LOSS;
    float* out_idx  = out + OFF_IDX;
    float* out_bin  = out + OFF_BIN;

    cudaMemsetAsync(out_bin, 0, NUM_EMBED * sizeof(float));

    k0_init<<<1, 1>>>();
    k_prep_c<<<NUM_EMBED / 128, 128>>>(ew);

    cudaFuncSetAttribute(k_main, cudaFuncAttributeMaxDynamicSharedMemorySize, SM_TOT);
    k_main<<<NBLK, 128, SM_TOT>>>(z, ew, out_zq, out_idx, out_bin);

    k4_loss<<<1, 32>>>(out_loss);
}